// round 2
// baseline (speedup 1.0000x reference)
#include <cuda_runtime.h>

// Problem constants (B=16, N=325, H=8, L=24, DK=DV=64)
#define L_    24
#define DK_   64
#define DV_   64
#define BNH_  (16 * 325 * 8)      /* 41600 tiles */
#define QK_   (L_ * DK_)          /* 1536 floats per Q/K/V tile */
#define MS_   (L_ * L_)           /* 576 floats per mask/res/scores tile */

#define SQ_STR 68                 /* padded row stride for Q/K/V smem (272B, 16B-aligned, bank-staggered) */
#define SS_STR 25                 /* padded row stride for transposed scores */

static const long long CTX_ELEMS = (long long)BNH_ * QK_;   // 63,897,600

__global__ __launch_bounds__(128, 1)
void satt_kernel(const float* __restrict__ Qg, const float* __restrict__ Kg,
                 const float* __restrict__ Vg, const float* __restrict__ Mg,
                 const float* __restrict__ Rg,
                 float* __restrict__ Cg, float* __restrict__ Sg)
{
    __shared__ float sQ[L_ * SQ_STR];
    __shared__ float sK[L_ * SQ_STR];
    __shared__ float sV[L_ * SQ_STR];
    __shared__ float sS[L_ * SS_STR];   // transposed masked scores, then attn: sS[k][q]
    __shared__ float sM[MS_];
    __shared__ float sR[MS_];

    const int tid   = threadIdx.x;
    const int wid   = tid >> 5;
    const int lane  = tid & 31;
    const int bid   = blockIdx.x;
    const int heavy = bid & 3;          // which warp does the GEMMs (SMSP load balance)
    const size_t qoff = (size_t)bid * QK_;
    const size_t moff = (size_t)bid * MS_;

    // ---- Phase 0: cooperative load of Q, K, V (float4, coalesced) ----
    {
        const float4* Q4 = reinterpret_cast<const float4*>(Qg + qoff);
        const float4* K4 = reinterpret_cast<const float4*>(Kg + qoff);
        const float4* V4 = reinterpret_cast<const float4*>(Vg + qoff);
#pragma unroll
        for (int it = 0; it < 3; ++it) {
            int e = tid + it * 128;          // float4 index 0..383
            int q = e >> 4;                  // row (16 float4 per 64-float row)
            int d = (e & 15) << 2;           // col
            *reinterpret_cast<float4*>(&sQ[q * SQ_STR + d]) = Q4[e];
            *reinterpret_cast<float4*>(&sK[q * SQ_STR + d]) = K4[e];
            *reinterpret_cast<float4*>(&sV[q * SQ_STR + d]) = V4[e];
        }
    }
    __syncthreads();

    // ---- Phase 1: heavy warp computes S = Q K^T (TQ=6 x TK=3 register tile);
    //      other warps prefetch mask/res into smem. ----
    float sacc[6][3];
    if (wid == heavy) {
        const int qt = lane >> 3;            // 0..3 -> q0 = qt*6
        const int kt = lane & 7;             // 0..7 -> k0 = kt*3
        const int q0 = qt * 6, k0 = kt * 3;
#pragma unroll
        for (int i = 0; i < 6; ++i)
#pragma unroll
            for (int j = 0; j < 3; ++j) sacc[i][j] = 0.0f;

#pragma unroll 4
        for (int d = 0; d < DK_; ++d) {
            float qv[6], kv[3];
#pragma unroll
            for (int i = 0; i < 6; ++i) qv[i] = sQ[(q0 + i) * SQ_STR + d];
#pragma unroll
            for (int j = 0; j < 3; ++j) kv[j] = sK[(k0 + j) * SQ_STR + d];
#pragma unroll
            for (int i = 0; i < 6; ++i)
#pragma unroll
                for (int j = 0; j < 3; ++j)
                    sacc[i][j] = fmaf(qv[i], kv[j], sacc[i][j]);
        }
    } else {
        // 96 threads load mask + res (144 float4 each)
        const float4* M4 = reinterpret_cast<const float4*>(Mg + moff);
        const float4* R4 = reinterpret_cast<const float4*>(Rg + moff);
        int hidx = (wid < heavy) ? tid : (tid - 32);   // 0..95
        for (int e = hidx; e < 144; e += 96) {
            reinterpret_cast<float4*>(sM)[e] = M4[e];
            reinterpret_cast<float4*>(sR)[e] = R4[e];
        }
    }
    __syncthreads();

    // ---- Phase 2: heavy warp epilogue: scale + res + mask, store transposed ----
    if (wid == heavy) {
        const int qt = lane >> 3;
        const int kt = lane & 7;
        const int q0 = qt * 6, k0 = kt * 3;
#pragma unroll
        for (int i = 0; i < 6; ++i) {
            const int q = q0 + i;
#pragma unroll
            for (int j = 0; j < 3; ++j) {
                const int k = k0 + j;
                float s = fmaf(sacc[i][j], 0.125f, sR[q * L_ + k]);
                if (sM[q * L_ + k] > 0.5f) s = -1e9f;
                sS[k * SS_STR + q] = s;
            }
        }
    }
    __syncthreads();

    // ---- Phase 3: coalesced store of masked scores (all threads) ----
    {
        float4* S4 = reinterpret_cast<float4*>(Sg + moff);
        for (int f = tid; f < 144; f += 128) {
            int e = f << 2;                  // element index = q*24 + k, k%4==0
            int q = e / 24;
            int k = e - q * 24;
            float4 o;
            o.x = sS[(k + 0) * SS_STR + q];
            o.y = sS[(k + 1) * SS_STR + q];
            o.z = sS[(k + 2) * SS_STR + q];
            o.w = sS[(k + 3) * SS_STR + q];
            S4[f] = o;
        }
    }
    __syncthreads();

    // ---- Phase 4: softmax over q (per k column = row of sS), in place ----
    if (wid == heavy && lane < L_) {
        float v[L_];
#pragma unroll
        for (int q = 0; q < L_; ++q) v[q] = sS[lane * SS_STR + q];
        float m = v[0];
#pragma unroll
        for (int q = 1; q < L_; ++q) m = fmaxf(m, v[q]);
        float sum = 0.0f;
#pragma unroll
        for (int q = 0; q < L_; ++q) { v[q] = __expf(v[q] - m); sum += v[q]; }
        const float r = 1.0f / sum;
#pragma unroll
        for (int q = 0; q < L_; ++q) sS[lane * SS_STR + q] = v[q] * r;
    }
    __syncthreads();

    // ---- Phase 5: heavy warp computes C = A V (TQ=6 x TV=8, v interleaved by 8) ----
    if (wid == heavy) {
        const int qt = lane >> 3;            // 0..3 -> q0 = qt*6
        const int vt = lane & 7;             // v = vt + 8*j
        const int q0 = qt * 6;
        float c[6][8];
#pragma unroll
        for (int i = 0; i < 6; ++i)
#pragma unroll
            for (int j = 0; j < 8; ++j) c[i][j] = 0.0f;

#pragma unroll 4
        for (int k = 0; k < L_; ++k) {
            float av[6], vv[8];
#pragma unroll
            for (int i = 0; i < 6; ++i) av[i] = sS[k * SS_STR + q0 + i];
#pragma unroll
            for (int j = 0; j < 8; ++j) vv[j] = sV[k * SQ_STR + vt + 8 * j];
#pragma unroll
            for (int i = 0; i < 6; ++i)
#pragma unroll
                for (int j = 0; j < 8; ++j)
                    c[i][j] = fmaf(av[i], vv[j], c[i][j]);
        }

        float* C = Cg + qoff;
#pragma unroll
        for (int i = 0; i < 6; ++i)
#pragma unroll
            for (int j = 0; j < 8; ++j)
                C[(q0 + i) * DV_ + vt + 8 * j] = c[i][j];
    }
}

extern "C" void kernel_launch(void* const* d_in, const int* in_sizes, int n_in,
                              void* d_out, int out_size)
{
    (void)in_sizes; (void)n_in; (void)out_size;
    const float* Q  = (const float*)d_in[0];
    const float* K  = (const float*)d_in[1];
    const float* V  = (const float*)d_in[2];
    const float* Mm = (const float*)d_in[3];
    const float* Ra = (const float*)d_in[4];
    float* ctx    = (float*)d_out;                 // (context, scores) concatenated
    float* scores = (float*)d_out + CTX_ELEMS;
    satt_kernel<<<BNH_, 128>>>(Q, K, V, Mm, Ra, ctx, scores);
}

// round 3
// speedup vs baseline: 1.1142x; 1.1142x over previous
#include <cuda_runtime.h>
#include <math_constants.h>

// Problem constants (B=16, N=325, H=8, L=24, DK=DV=64)
#define L_    24
#define DK_   64
#define DV_   64
#define BNH_  41600
#define QK_   (L_ * DK_)          /* 1536 floats per Q/K/V tile */
#define MS_   (L_ * L_)           /* 576 floats per mask/res/scores tile */

#define SQ  68                    /* padded row stride for Q/K/V smem */
#define SSn 25                    /* padded row stride for transposed scores */

static const long long CTX_ELEMS = (long long)BNH_ * QK_;   // 63,897,600

__global__ __launch_bounds__(128, 8)
void satt_kernel(const float* __restrict__ Qg, const float* __restrict__ Kg,
                 const float* __restrict__ Vg, const float* __restrict__ Mg,
                 const float* __restrict__ Rg,
                 float* __restrict__ Cg, float* __restrict__ Sg)
{
    __shared__ float sQ[L_ * SQ];
    __shared__ float sK[L_ * SQ];
    __shared__ float sV[L_ * SQ];
    __shared__ float sS[L_ * SSn];   // transposed scores then attn: sS[k][q]
    __shared__ float sM[MS_];
    __shared__ float sR[MS_];

    const int tid  = threadIdx.x;
    const int wid  = tid >> 5;
    const int lane = tid & 31;
    const int bid  = blockIdx.x;
    const int vw   = wid ^ ((bid & 1) << 1);   // logical warp role (SMSP balance)
    const size_t qoff = (size_t)bid * QK_;
    const size_t moff = (size_t)bid * MS_;

    // ---------- S0: front-batched loads of Q, K, V, mask, res ----------
    {
        const float4* Q4 = reinterpret_cast<const float4*>(Qg + qoff);
        const float4* K4 = reinterpret_cast<const float4*>(Kg + qoff);
        const float4* V4 = reinterpret_cast<const float4*>(Vg + qoff);
#pragma unroll
        for (int it = 0; it < 3; ++it) {
            int e = tid + it * 128;          // 0..383
            int q = e >> 4;
            int d = (e & 15) << 2;
            *reinterpret_cast<float4*>(&sQ[q * SQ + d]) = Q4[e];
            *reinterpret_cast<float4*>(&sK[q * SQ + d]) = K4[e];
            *reinterpret_cast<float4*>(&sV[q * SQ + d]) = V4[e];
        }
        const float4* M4 = reinterpret_cast<const float4*>(Mg + moff);
        const float4* R4 = reinterpret_cast<const float4*>(Rg + moff);
        reinterpret_cast<float4*>(sM)[tid] = M4[tid];
        reinterpret_cast<float4*>(sR)[tid] = R4[tid];
        if (tid < 16) {
            reinterpret_cast<float4*>(sM)[tid + 128] = M4[tid + 128];
            reinterpret_cast<float4*>(sR)[tid + 128] = R4[tid + 128];
        }
    }
    __syncthreads();

    // ---------- S1+S2: QK^T on 2 warps (12x24 each, TQ=3 x TK=3/lane), fused epilogue ----------
    if (vw < 2) {
        const int q0 = vw * 12 + (lane >> 3) * 3;
        const int k0 = (lane & 7) * 3;
        float acc[3][3] = {};
#pragma unroll
        for (int d = 0; d < DK_; d += 4) {
            float4 qv[3], kv[3];
#pragma unroll
            for (int i = 0; i < 3; ++i) qv[i] = *reinterpret_cast<const float4*>(&sQ[(q0 + i) * SQ + d]);
#pragma unroll
            for (int j = 0; j < 3; ++j) kv[j] = *reinterpret_cast<const float4*>(&sK[(k0 + j) * SQ + d]);
#pragma unroll
            for (int i = 0; i < 3; ++i)
#pragma unroll
                for (int j = 0; j < 3; ++j) {
                    acc[i][j] = fmaf(qv[i].x, kv[j].x, acc[i][j]);
                    acc[i][j] = fmaf(qv[i].y, kv[j].y, acc[i][j]);
                    acc[i][j] = fmaf(qv[i].z, kv[j].z, acc[i][j]);
                    acc[i][j] = fmaf(qv[i].w, kv[j].w, acc[i][j]);
                }
        }
        // epilogue: scale + res + mask, store transposed
#pragma unroll
        for (int i = 0; i < 3; ++i) {
            const int q = q0 + i;
#pragma unroll
            for (int j = 0; j < 3; ++j) {
                const int k = k0 + j;
                float s = fmaf(acc[i][j], 0.125f, sR[q * L_ + k]);
                if (sM[q * L_ + k] > 0.5f) s = -1e9f;
                sS[k * SSn + q] = s;
            }
        }
    }
    __syncthreads();

    // ---------- S3: coalesced global store of masked scores + softmax reads ----------
    {
        float4* S4 = reinterpret_cast<float4*>(Sg + moff);
        {
            int f = tid;
            int q = f / 6, k = (f % 6) * 4;
            float4 o;
            o.x = sS[(k + 0) * SSn + q];
            o.y = sS[(k + 1) * SSn + q];
            o.z = sS[(k + 2) * SSn + q];
            o.w = sS[(k + 3) * SSn + q];
            S4[f] = o;
        }
        if (tid < 16) {
            int f = tid + 128;
            int q = f / 6, k = (f % 6) * 4;
            float4 o;
            o.x = sS[(k + 0) * SSn + q];
            o.y = sS[(k + 1) * SSn + q];
            o.z = sS[(k + 2) * SSn + q];
            o.w = sS[(k + 3) * SSn + q];
            S4[f] = o;
        }
    }
    // softmax over q for 6 k-columns per warp (values held in regs across the barrier)
    float nv[6];
#pragma unroll
    for (int r = 0; r < 6; ++r) {
        const int k = vw * 6 + r;
        float v = (lane < L_) ? sS[k * SSn + lane] : -CUDART_INF_F;
        float m = v;
#pragma unroll
        for (int o = 16; o; o >>= 1) m = fmaxf(m, __shfl_xor_sync(0xffffffffu, m, o));
        float e = (lane < L_) ? __expf(v - m) : 0.0f;
        float s = e;
#pragma unroll
        for (int o = 16; o; o >>= 1) s += __shfl_xor_sync(0xffffffffu, s, o);
        nv[r] = e * __fdividef(1.0f, s);
    }
    __syncthreads();
    if (lane < L_) {
#pragma unroll
        for (int r = 0; r < 6; ++r) sS[(vw * 6 + r) * SSn + lane] = nv[r];
    }
    __syncthreads();

    // ---------- S4: C = A·V on all 4 warps (thread grid 8x16, TQ=3 x TV=4) ----------
    {
        const int q0 = (tid >> 4) * 3;
        const int v0 = (tid & 15) * 4;
        float c[3][4] = {};
#pragma unroll 4
        for (int k = 0; k < L_; ++k) {
            const float a0 = sS[k * SSn + q0];
            const float a1 = sS[k * SSn + q0 + 1];
            const float a2 = sS[k * SSn + q0 + 2];
            const float4 vv = *reinterpret_cast<const float4*>(&sV[k * SQ + v0]);
            c[0][0] = fmaf(a0, vv.x, c[0][0]);
            c[0][1] = fmaf(a0, vv.y, c[0][1]);
            c[0][2] = fmaf(a0, vv.z, c[0][2]);
            c[0][3] = fmaf(a0, vv.w, c[0][3]);
            c[1][0] = fmaf(a1, vv.x, c[1][0]);
            c[1][1] = fmaf(a1, vv.y, c[1][1]);
            c[1][2] = fmaf(a1, vv.z, c[1][2]);
            c[1][3] = fmaf(a1, vv.w, c[1][3]);
            c[2][0] = fmaf(a2, vv.x, c[2][0]);
            c[2][1] = fmaf(a2, vv.y, c[2][1]);
            c[2][2] = fmaf(a2, vv.z, c[2][2]);
            c[2][3] = fmaf(a2, vv.w, c[2][3]);
        }
        float* C = Cg + qoff;
#pragma unroll
        for (int i = 0; i < 3; ++i) {
            float4 o;
            o.x = c[i][0]; o.y = c[i][1]; o.z = c[i][2]; o.w = c[i][3];
            *reinterpret_cast<float4*>(&C[(q0 + i) * DV_ + v0]) = o;
        }
    }
}

extern "C" void kernel_launch(void* const* d_in, const int* in_sizes, int n_in,
                              void* d_out, int out_size)
{
    (void)in_sizes; (void)n_in; (void)out_size;
    const float* Q  = (const float*)d_in[0];
    const float* K  = (const float*)d_in[1];
    const float* V  = (const float*)d_in[2];
    const float* Mm = (const float*)d_in[3];
    const float* Ra = (const float*)d_in[4];
    float* ctx    = (float*)d_out;                 // (context, scores) concatenated
    float* scores = (float*)d_out + CTX_ELEMS;
    satt_kernel<<<BNH_, 128>>>(Q, K, V, Mm, Ra, ctx, scores);
}

// round 4
// speedup vs baseline: 1.2531x; 1.1247x over previous
#include <cuda_runtime.h>

// Problem constants (B=16, N=325, H=8, L=24, DK=DV=64)
#define L_    24
#define DK_   64
#define DV_   64
#define BNH_  41600
#define QK_   (L_ * DK_)          /* 1536 floats per Q/K/V tile */
#define MS_   (L_ * L_)           /* 576 floats per mask/res/scores tile */

#define SQ  68                    /* padded row stride for Q/K smem (multi-row column reads) */
#define SS  28                    /* padded row stride for scores (natural [q][k], 16B aligned) */

static const long long CTX_ELEMS = (long long)BNH_ * QK_;   // 63,897,600

__global__ __launch_bounds__(128, 8)
void satt_kernel(const float* __restrict__ Qg, const float* __restrict__ Kg,
                 const float* __restrict__ Vg, const float* __restrict__ Mg,
                 const float* __restrict__ Rg,
                 float* __restrict__ Cg, float* __restrict__ Sg)
{
    __shared__ float sQ[L_ * SQ];
    __shared__ float sK[L_ * SQ];
    __shared__ float sV[L_ * DV_];      // no pad: all accesses row-wise
    __shared__ float sS[L_ * SS];       // raw masked scores, natural [q][k]
    __shared__ float sMR[2 * MS_];      // mask | res;  later reused as sA (normalized attn, stride SS)
    __shared__ float sPmax[2 * 32];
    __shared__ float sPsum[2 * 32];

    float* const sM = sMR;
    float* const sR = sMR + MS_;
    float* const sA = sMR;              // alias: valid after mask/res are dead

    const int tid  = threadIdx.x;
    const int wid  = tid >> 5;
    const int lane = tid & 31;
    const int bid  = blockIdx.x;
    const int vw   = wid ^ (bid & 3);   // logical role, rotated for SMSP balance
    const size_t qoff = (size_t)bid * QK_;
    const size_t moff = (size_t)bid * MS_;

    // ---------- S0: front-batched loads of Q, K, V, mask, res ----------
    {
        const float4* Q4 = reinterpret_cast<const float4*>(Qg + qoff);
        const float4* K4 = reinterpret_cast<const float4*>(Kg + qoff);
        const float4* V4 = reinterpret_cast<const float4*>(Vg + qoff);
#pragma unroll
        for (int it = 0; it < 3; ++it) {
            int e = tid + it * 128;          // 0..383
            int q = e >> 4;
            int d = (e & 15) << 2;
            *reinterpret_cast<float4*>(&sQ[q * SQ + d]) = Q4[e];
            *reinterpret_cast<float4*>(&sK[q * SQ + d]) = K4[e];
            reinterpret_cast<float4*>(sV)[e] = V4[e];
        }
        const float4* M4 = reinterpret_cast<const float4*>(Mg + moff);
        const float4* R4 = reinterpret_cast<const float4*>(Rg + moff);
        reinterpret_cast<float4*>(sM)[tid] = M4[tid];
        reinterpret_cast<float4*>(sR)[tid] = R4[tid];
        if (tid < 16) {
            reinterpret_cast<float4*>(sM)[tid + 128] = M4[tid + 128];
            reinterpret_cast<float4*>(sR)[tid + 128] = R4[tid + 128];
        }
    }
    __syncthreads();

    // ---------- P1: QK^T on warps {0,1} (12x24 each, TQ=3 x TK=3/lane) + fused epilogue ----------
    if (vw < 2) {
        const int q0 = vw * 12 + (lane >> 3) * 3;
        const int k0 = (lane & 7) * 3;
        float acc[3][3] = {};
#pragma unroll
        for (int d = 0; d < DK_; d += 4) {
            float4 qv[3], kv[3];
#pragma unroll
            for (int i = 0; i < 3; ++i) qv[i] = *reinterpret_cast<const float4*>(&sQ[(q0 + i) * SQ + d]);
#pragma unroll
            for (int j = 0; j < 3; ++j) kv[j] = *reinterpret_cast<const float4*>(&sK[(k0 + j) * SQ + d]);
#pragma unroll
            for (int i = 0; i < 3; ++i)
#pragma unroll
                for (int j = 0; j < 3; ++j) {
                    acc[i][j] = fmaf(qv[i].x, kv[j].x, acc[i][j]);
                    acc[i][j] = fmaf(qv[i].y, kv[j].y, acc[i][j]);
                    acc[i][j] = fmaf(qv[i].z, kv[j].z, acc[i][j]);
                    acc[i][j] = fmaf(qv[i].w, kv[j].w, acc[i][j]);
                }
        }
        // epilogue: scale + res + mask -> raw scores, natural layout
#pragma unroll
        for (int i = 0; i < 3; ++i) {
            const int q = q0 + i;
#pragma unroll
            for (int j = 0; j < 3; ++j) {
                const int k = k0 + j;
                float s = fmaf(acc[i][j], 0.125f, sR[q * L_ + k]);
                if (sM[q * L_ + k] > 0.5f) s = -1e9f;
                sS[q * SS + k] = s;
            }
        }
    }
    __syncthreads();

    // ---------- P2: overlap — warps{0,1}: softmax over q; warps{2,3}: raw scores -> global ----------
    const int r  = vw & 1;              // sub-role within pair
    float v[12];
    if (vw < 2) {
        // read 12 rows, lane = k (conflict-free)
        if (lane < L_) {
#pragma unroll
            for (int i = 0; i < 12; ++i) v[i] = sS[(r * 12 + i) * SS + lane];
            float m = v[0];
#pragma unroll
            for (int i = 1; i < 12; ++i) m = fmaxf(m, v[i]);
            sPmax[r * 32 + lane] = m;
        }
    } else {
        const int hw = r * 32 + lane;    // 0..63
        float4* S4 = reinterpret_cast<float4*>(Sg + moff);
#pragma unroll
        for (int it = 0; it < 2; ++it) {
            int f = hw + it * 64;        // 0..127
            int q = f / 6, k = (f % 6) * 4;
            S4[f] = *reinterpret_cast<const float4*>(&sS[q * SS + k]);
        }
    }
    __syncthreads();

    if (vw < 2) {
        if (lane < L_) {
            const float m = fmaxf(sPmax[lane], sPmax[32 + lane]);
            float s = 0.0f;
#pragma unroll
            for (int i = 0; i < 12; ++i) { v[i] = __expf(v[i] - m); s += v[i]; }
            sPsum[r * 32 + lane] = s;
        }
    } else {
        const int hw = r * 32 + lane;
        if (hw < 16) {
            int f = hw + 128;            // 128..143
            int q = f / 6, k = (f % 6) * 4;
            float4* S4 = reinterpret_cast<float4*>(Sg + moff);
            S4[f] = *reinterpret_cast<const float4*>(&sS[q * SS + k]);
        }
    }
    __syncthreads();

    if (vw < 2 && lane < L_) {
        const float z = sPsum[lane] + sPsum[32 + lane];
        const float w = __fdividef(1.0f, z);
#pragma unroll
        for (int i = 0; i < 12; ++i) sA[(r * 12 + i) * SS + lane] = v[i] * w;
    }
    __syncthreads();

    // ---------- P3: C = A·V on warps {2,3} (each 24q x 32v, TQ=6 x TV=4, all float4) ----------
    if (vw >= 2) {
        const int q0 = (lane >> 3) * 6;          // 4 q-groups of 6
        const int v0 = r * 32 + (lane & 7) * 4;  // warp half of v
        float4 c[6];
#pragma unroll
        for (int i = 0; i < 6; ++i) c[i] = make_float4(0.f, 0.f, 0.f, 0.f);

#pragma unroll
        for (int kk = 0; kk < L_; kk += 4) {
            float4 vr[4];
#pragma unroll
            for (int m = 0; m < 4; ++m)
                vr[m] = *reinterpret_cast<const float4*>(&sV[(kk + m) * DV_ + v0]);
#pragma unroll
            for (int i = 0; i < 6; ++i) {
                const float4 a = *reinterpret_cast<const float4*>(&sA[(q0 + i) * SS + kk]);
                c[i].x = fmaf(a.x, vr[0].x, c[i].x);
                c[i].y = fmaf(a.x, vr[0].y, c[i].y);
                c[i].z = fmaf(a.x, vr[0].z, c[i].z);
                c[i].w = fmaf(a.x, vr[0].w, c[i].w);
                c[i].x = fmaf(a.y, vr[1].x, c[i].x);
                c[i].y = fmaf(a.y, vr[1].y, c[i].y);
                c[i].z = fmaf(a.y, vr[1].z, c[i].z);
                c[i].w = fmaf(a.y, vr[1].w, c[i].w);
                c[i].x = fmaf(a.z, vr[2].x, c[i].x);
                c[i].y = fmaf(a.z, vr[2].y, c[i].y);
                c[i].z = fmaf(a.z, vr[2].z, c[i].z);
                c[i].w = fmaf(a.z, vr[2].w, c[i].w);
                c[i].x = fmaf(a.w, vr[3].x, c[i].x);
                c[i].y = fmaf(a.w, vr[3].y, c[i].y);
                c[i].z = fmaf(a.w, vr[3].z, c[i].z);
                c[i].w = fmaf(a.w, vr[3].w, c[i].w);
            }
        }
        float* C = Cg + qoff;
#pragma unroll
        for (int i = 0; i < 6; ++i)
            *reinterpret_cast<float4*>(&C[(q0 + i) * DV_ + v0]) = c[i];
    }
}

extern "C" void kernel_launch(void* const* d_in, const int* in_sizes, int n_in,
                              void* d_out, int out_size)
{
    (void)in_sizes; (void)n_in; (void)out_size;
    const float* Q  = (const float*)d_in[0];
    const float* K  = (const float*)d_in[1];
    const float* V  = (const float*)d_in[2];
    const float* Mm = (const float*)d_in[3];
    const float* Ra = (const float*)d_in[4];
    float* ctx    = (float*)d_out;                 // (context, scores) concatenated
    float* scores = (float*)d_out + CTX_ELEMS;
    satt_kernel<<<BNH_, 128>>>(Q, K, V, Mm, Ra, ctx, scores);
}